// round 17
// baseline (speedup 1.0000x reference)
#include <cuda_runtime.h>
#include <cstdint>

// Encoding: B=64, C=512, N=784, K=32. x:(B,C,N) f32; out:(B,K,C) f32.
// K1: TS=32, x_s [c][n] double buffer filled by cp.async.16B; logits mma tf32 +
//     softmax -> A ([b][n][k], tf32) + wsum. 3 syncs per 32-n tile.
// K2 (round-10 proven): out = A^T x, 64-c blocks, double-buffered, fused epilogue.

#define CDIM 512
#define KD 32
#define NPIX 784
#define BDIM 64
#define CH 7
#define TILES 25            // 25 tiles of 32 n (last padded to 800)
#define XR 36               // x_s row stride (floats), [c][n] layout
#define XBUF (512 * XR)     // 18432 floats per buffer
#define K1_SMEM_BYTES ((2 * XBUF + 1088 + 1024 + 64 + 32 + 32 + 256) * 4)

__device__ float g_A[(size_t)BDIM * NPIX * KD];     // 6.4 MB, [b][n][k]
__device__ float g_wsum[BDIM * CH * KD];

__device__ __forceinline__ float rtf32(float v) {
    asm("cvt.rna.tf32.f32 %0, %1;" : "=f"(v) : "f"(v));
    return v;
}
__device__ __forceinline__ void mma8(float* d, uint32_t a0, uint32_t a1,
                                     uint32_t a2, uint32_t a3,
                                     uint32_t b0, uint32_t b1) {
    asm volatile(
        "mma.sync.aligned.m16n8k8.row.col.f32.tf32.tf32.f32 "
        "{%0,%1,%2,%3}, {%4,%5,%6,%7}, {%8,%9}, {%0,%1,%2,%3};"
        : "+f"(d[0]), "+f"(d[1]), "+f"(d[2]), "+f"(d[3])
        : "r"(a0), "r"(a1), "r"(a2), "r"(a3), "r"(b0), "r"(b1));
}
__device__ __forceinline__ uint32_t smem_u32(const void* p) {
    uint32_t a;
    asm("{ .reg .u64 t; cvta.to.shared.u64 t, %1; cvt.u32.u64 %0, t; }" : "=r"(a) : "l"(p));
    return a;
}
__device__ __forceinline__ void cpa16(uint32_t sa, const void* g, int szbytes) {
    asm volatile("cp.async.ca.shared.global [%0], [%1], 16, %2;"
                 :: "r"(sa), "l"(g), "r"(szbytes));
}
#define CPA_COMMIT() asm volatile("cp.async.commit_group;" ::: "memory")
#define CPA_WAIT0()  asm volatile("cp.async.wait_group 0;" ::: "memory")
#define BITS(f) __float_as_uint(f)

// =========================== K1: logits + softmax (TS=32) ===========================
__global__ __launch_bounds__(256) void enc_k1(const float* __restrict__ x,
                                              const float* __restrict__ cw,
                                              const float* __restrict__ scale) {
    extern __shared__ float sm[];
    float* x_sm   = sm;                  // 2 * XBUF, [c][n] stride XR
    float* xc_s   = sm + 2 * XBUF;       // 32*34
    float* red_s  = xc_s + 1088;         // 1024
    float* part_s = red_s + 1024;        // 64 (xsq per half)
    float* csq_s  = part_s + 64;         // 32
    float* scl_s  = csq_s + 32;          // 32
    float* wsum_s = scl_s + 32;          // 8*32

    const int b = blockIdx.x / CH, ch = blockIdx.x % CH;
    const int tile0 = ch * TILES / CH, tile1 = (ch + 1) * TILES / CH;
    const int t = threadIdx.x, w = t >> 5, l = t & 31;
    const int kt = w & 3, h = w >> 2;         // warp = (k-tile, c-half)

    if (t < KD) scl_s[t] = __ldg(&scale[t]);
#pragma unroll
    for (int kk = 0; kk < 4; kk++) {
        int k = 4 * w + kk;
        float s = 0.f;
#pragma unroll
        for (int q = 0; q < 4; q++) {
            float4 v = __ldg((const float4*)&cw[k * CDIM + l * 16 + 4 * q]);
            float e0 = rtf32(v.x), e1 = rtf32(v.y), e2 = rtf32(v.z), e3 = rtf32(v.w);
            s += e0 * e0 + e1 * e1 + e2 * e2 + e3 * e3;
        }
#pragma unroll
        for (int o = 16; o; o >>= 1) s += __shfl_xor_sync(~0u, s, o);
        if (l == 0) csq_s[k] = s;
    }

    // persistent codeword B-fragments (tf32): warp covers k=8kt..+7, c-half h
    uint32_t cwf0[32], cwf1[32];
    const int crow = kt * 8 + (l >> 2), cp = l & 3;
#pragma unroll
    for (int s = 0; s < 32; s++) {
        int c = h * 256 + 8 * s + cp;
        cwf0[s] = BITS(rtf32(__ldg(&cw[crow * CDIM + c])));
        cwf1[s] = BITS(rtf32(__ldg(&cw[crow * CDIM + c + 4])));
    }

    const float* xb = x + (size_t)b * CDIM * NPIX;
    const int o8 = t & 3, cs = t >> 2;        // staging: n-octet, c-row base
    const uint32_t xaddr = smem_u32(x_sm);

#define K1_ISSUE(tl_) do { \
        int n0_ = (tl_) * 32, bi_ = (tl_) & 1; \
        _Pragma("unroll") for (int i = 0; i < 8; i++) { \
            int c_ = cs + 64 * i; \
            _Pragma("unroll") for (int q = 0; q < 2; q++) { \
                int nn_ = n0_ + 8 * o8 + 4 * q; \
                cpa16(xaddr + 4u * (bi_ * XBUF + c_ * XR + 8 * o8 + 4 * q), \
                      xb + (size_t)c_ * NPIX + (nn_ < NPIX ? nn_ : 0), \
                      nn_ + 4 <= NPIX ? 16 : 0); \
            } } \
        CPA_COMMIT(); \
    } while (0)

    K1_ISSUE(tile0);
    CPA_WAIT0();
    __syncthreads();

    float wsum_acc = 0.f;
    const int rn = l >> 2;

    for (int tl = tile0; tl < tile1; tl++) {
        const float* xbuf = x_sm + (tl & 1) * XBUF;
        if (tl + 1 < tile1) { K1_ISSUE(tl + 1); }   // overlaps whole tile body

        // phase 1: xc = x . cw^T for both 16-n halves (raw fp32 -> HW tf32)
        float d4[2][4];
#pragma unroll
        for (int nh = 0; nh < 2; nh++) {
            float dA[4] = {0.f, 0.f, 0.f, 0.f}, dB[4] = {0.f, 0.f, 0.f, 0.f};
            const int nb = nh * 16 + rn;
#pragma unroll
            for (int s = 0; s < 32; s++) {
                int c = h * 256 + 8 * s + cp;
                float f0 = xbuf[c * XR + nb];
                float f1 = xbuf[c * XR + nb + 8];
                float f2 = xbuf[(c + 4) * XR + nb];
                float f3 = xbuf[(c + 4) * XR + nb + 8];
                mma8((s & 1) ? dB : dA, BITS(f0), BITS(f1), BITS(f2), BITS(f3),
                     cwf0[s], cwf1[s]);
            }
#pragma unroll
            for (int i = 0; i < 4; i++) d4[nh][i] = dA[i] + dB[i];
        }

        // xsq: kt==0 warps re-read their fragments (conflict-free) and reduce
        if (kt == 0) {
#pragma unroll
            for (int nh = 0; nh < 2; nh++) {
                float v0 = 0.f, v1 = 0.f;
                const int nb = nh * 16 + rn;
#pragma unroll
                for (int s = 0; s < 32; s++) {
                    int c = h * 256 + 8 * s + cp;
                    float f0 = xbuf[c * XR + nb];
                    float f1 = xbuf[c * XR + nb + 8];
                    float f2 = xbuf[(c + 4) * XR + nb];
                    float f3 = xbuf[(c + 4) * XR + nb + 8];
                    v0 = fmaf(f0, f0, fmaf(f2, f2, v0));
                    v1 = fmaf(f1, f1, fmaf(f3, f3, v1));
                }
                v0 += __shfl_xor_sync(~0u, v0, 1); v0 += __shfl_xor_sync(~0u, v0, 2);
                v1 += __shfl_xor_sync(~0u, v1, 1); v1 += __shfl_xor_sync(~0u, v1, 2);
                if (cp == 0) {
                    part_s[h * 32 + nh * 16 + rn] = v0;
                    part_s[h * 32 + nh * 16 + rn + 8] = v1;
                }
            }
        }
        if (h == 1) {
#pragma unroll
            for (int nh = 0; nh < 2; nh++)
                *(float4*)&red_s[(nh * 128 + kt * 32 + l) * 4] =
                    make_float4(d4[nh][0], d4[nh][1], d4[nh][2], d4[nh][3]);
        }
        __syncthreads();
        if (h == 0) {
#pragma unroll
            for (int nh = 0; nh < 2; nh++) {
                float4 rr4 = *(const float4*)&red_s[(nh * 128 + kt * 32 + l) * 4];
                int cc = kt * 8 + 2 * cp;
                *(float2*)&xc_s[(nh * 16 + rn) * 34 + cc] =
                    make_float2(d4[nh][0] + rr4.x, d4[nh][1] + rr4.y);
                *(float2*)&xc_s[(nh * 16 + rn + 8) * 34 + cc] =
                    make_float2(d4[nh][2] + rr4.z, d4[nh][3] + rr4.w);
            }
        }
        __syncthreads();

        // softmax: warp w rows {w, w+8, w+16, w+24}, lane = k
        const int n0 = tl * 32;
#pragma unroll
        for (int r = 0; r < 4; r++) {
            int n = w + 8 * r;
            if (n0 + n < NPIX) {                  // warp-uniform guard
                float xs = part_s[n] + part_s[32 + n];
                float xcv = xc_s[n * 34 + l];
                float dd = scl_s[l] * (xs - 2.f * xcv + csq_s[l]);
                float m = dd;
#pragma unroll
                for (int oo = 16; oo; oo >>= 1) m = fmaxf(m, __shfl_xor_sync(~0u, m, oo));
                float e = __expf(dd - m);
                float ssum = e;
#pragma unroll
                for (int oo = 16; oo; oo >>= 1) ssum += __shfl_xor_sync(~0u, ssum, oo);
                float a = rtf32(__fdividef(e, ssum));
                wsum_acc += a;
                g_A[((size_t)b * NPIX + n0 + n) * KD + l] = a;   // coalesced
            }
        }
        CPA_WAIT0();          // next tile landed (overlapped with everything above)
        __syncthreads();      // publish next buffer; fence xc_s/red_s/part_s reuse
    }

    wsum_s[w * KD + l] = wsum_acc;
    __syncthreads();
    if (t < KD) {
        float s = 0.f;
#pragma unroll
        for (int ww = 0; ww < 8; ww++) s += wsum_s[ww * KD + t];
        g_wsum[(b * CH + ch) * KD + t] = s;
    }
}

// ==== K2: out = A^T x, 64-c blocks, double-buffered, fused epilogue (round-10) ====
// x_s: n-group j (=n/4, 0..7) major, stride 66 float4; (j, c, n%4) at (j*66+c)*4 + n%4.
__global__ __launch_bounds__(256) void enc_k2(const float* __restrict__ x,
                                              const float* __restrict__ cw,
                                              float* __restrict__ out) {
    const int b = blockIdx.x >> 3, cb = blockIdx.x & 7;   // cb: 64-c block
    const int t = threadIdx.x, w = t >> 5, l = t & 31;
    const int mt = w & 1, cq = w >> 1;   // warp = (k-half 16, c-quarter 16)

    __shared__ float A_s[2][32 * 40];      // [32n][32k], stride 40
    __shared__ float x_s[2][8 * 66 * 4];   // blocked, 2112 floats/buf
    __shared__ float wsum_s[KD];

    if (t < KD) {
        float s = 0.f;
#pragma unroll
        for (int ch = 0; ch < CH; ch++) s += g_wsum[(b * CH + ch) * KD + t];
        wsum_s[t] = s;
    }

    float acc[2][4];
#pragma unroll
    for (int i = 0; i < 2; i++)
#pragma unroll
        for (int j = 0; j < 4; j++) acc[i][j] = 0.f;

    const float* xb = x + ((size_t)b * CDIM + cb * 64) * NPIX;
    const float* Ab = g_A + (size_t)b * NPIX * KD;
    const int ar = t >> 3, ak4 = t & 7;   // A staging: n row, k-float4
    const int xc_ = t >> 2, xj = t & 3;   // x staging: c row, n-group (and +4)

#define K2_LDG(n0, av, v0, v1) do { \
        av = ((n0) + ar < NPIX) \
            ? __ldg((const float4*)&Ab[(size_t)((n0) + ar) * KD + 4 * ak4]) \
            : make_float4(0.f, 0.f, 0.f, 0.f); \
        v0 = ((n0) + 4 * xj < NPIX) \
            ? __ldg((const float4*)&xb[(size_t)xc_ * NPIX + (n0) + 4 * xj]) \
            : make_float4(0.f, 0.f, 0.f, 0.f); \
        v1 = ((n0) + 4 * (xj + 4) < NPIX) \
            ? __ldg((const float4*)&xb[(size_t)xc_ * NPIX + (n0) + 4 * (xj + 4)]) \
            : make_float4(0.f, 0.f, 0.f, 0.f); \
    } while (0)

#define K2_STS(bi, av, v0, v1) do { \
        *(float4*)&A_s[bi][ar * 40 + 4 * ak4] = av; \
        *(float4*)&x_s[bi][(xj * 66 + xc_) * 4] = v0; \
        *(float4*)&x_s[bi][((xj + 4) * 66 + xc_) * 4] = v1; \
    } while (0)

    {   // prologue: stage tile 0 into buffer 0
        float4 av, v0, v1;
        K2_LDG(0, av, v0, v1);
        K2_STS(0, av, v0, v1);
    }
    __syncthreads();

    const int q3 = l & 3, c7 = l >> 2;

    for (int tl = 0; tl < 25; tl++) {
        const int cur = tl & 1;
        float4 av, v0, v1;
        if (tl < 24) { K2_LDG((tl + 1) * 32, av, v0, v1); }   // overlap with mma

#pragma unroll
        for (int ks = 0; ks < 4; ks++) {
            int pn = 8 * ks + q3;
            uint32_t a0 = BITS(A_s[cur][pn * 40 + mt * 16 + c7]);
            uint32_t a1 = BITS(A_s[cur][pn * 40 + mt * 16 + c7 + 8]);
            uint32_t a2 = BITS(A_s[cur][(pn + 4) * 40 + mt * 16 + c7]);
            uint32_t a3 = BITS(A_s[cur][(pn + 4) * 40 + mt * 16 + c7 + 8]);
#pragma unroll
            for (int nt = 0; nt < 2; nt++) {
                int crow = cq * 16 + nt * 8 + c7;
                uint32_t b0 = BITS(x_s[cur][((2 * ks) * 66 + crow) * 4 + q3]);
                uint32_t b1 = BITS(x_s[cur][((2 * ks + 1) * 66 + crow) * 4 + q3]);
                mma8(acc[nt], a0, a1, a2, a3, b0, b1);
            }
        }
        if (tl < 24) { K2_STS(1 - cur, av, v0, v1); }   // write other buffer
        __syncthreads();
    }

    // fused epilogue: out = acc - wsum*cw
    const int k0 = mt * 16 + c7;
#pragma unroll
    for (int nt = 0; nt < 2; nt++) {
        int c = cb * 64 + cq * 16 + nt * 8 + 2 * q3;
#pragma unroll
        for (int half = 0; half < 2; half++) {
            int k = k0 + 8 * half;
            float2 cv = __ldg((const float2*)&cw[k * CDIM + c]);
            float ws = wsum_s[k];
            float2 o;
            o.x = acc[nt][2 * half]     - ws * cv.x;
            o.y = acc[nt][2 * half + 1] - ws * cv.y;
            *(float2*)&out[((size_t)b * KD + k) * CDIM + c] = o;
        }
    }
}

extern "C" void kernel_launch(void* const* d_in, const int* in_sizes, int n_in,
                              void* d_out, int out_size) {
    const float* x     = (const float*)d_in[0];
    const float* cw    = (const float*)d_in[1];
    const float* scale = (const float*)d_in[2];
    static int configured = 0;
    if (!configured) {
        cudaFuncSetAttribute(enc_k1, cudaFuncAttributeMaxDynamicSharedMemorySize,
                             K1_SMEM_BYTES);
        configured = 1;
    }
    enc_k1<<<BDIM * CH, 256, K1_SMEM_BYTES>>>(x, cw, scale);
    enc_k2<<<BDIM * 8, 256>>>(x, cw, (float*)d_out);
}